// round 2
// baseline (speedup 1.0000x reference)
#include <cuda_runtime.h>
#include <math.h>

// Problem constants
#define BATCH    64
#define IN_CAPS  2048
#define IN_DIM   8
#define NC       32      // num output capsules
#define OUT_DIM  16
#define IB       32      // input-capsules per CTA
#define NIB      (IN_CAPS / IB)          // 64 i-blocks
#define BTILE    16      // batch rows per CTA
#define NBT      (BATCH / BTILE)         // 4 batch tiles
#define NV       (BATCH * NC * OUT_DIM)  // 32768 floats per s / v tensor

// Scratch (static device globals — no allocation allowed)
__device__ float g_s[3][NV];                       // raw weighted sums per routing iter
__device__ float g_v[2][NV];                       // squashed v0, v1
__device__ float g_logits[(size_t)BATCH * IN_CAPS * NC];  // b-logits after iter 1 (16MB)

__global__ void zero_kernel() {
    int idx = blockIdx.x * blockDim.x + threadIdx.x;
    if (idx < 3 * NV) ((float*)g_s)[idx] = 0.0f;
}

// P = routing pass index (0,1,2).
// Thread map: lane = capsule n (0..31); warp g (0..7) owns 2 batch rows.
// CTA = (i-block of 32 input capsules) x (batch tile of 16).
template <int P>
__global__ void __launch_bounds__(256)
pass_kernel(const float* __restrict__ x, const float* __restrict__ W) {
    // W tile: 32 rows (n) of 128 floats (d*16+e), padded to 132 floats/row.
    // Row stride 528B -> lane n's float4 reads land on distinct 16B groups
    // within each quarter-warp (conflict-free LDS.128).
    __shared__ float4 Wsm4[32 * 33];
    __shared__ float  xsm[BTILE][IN_DIM];
    float* Wsm = (float*)Wsm4;

    const int tid   = threadIdx.x;
    const int n     = tid & 31;
    const int g     = tid >> 5;                 // warp id 0..7
    const int btile = blockIdx.y;
    const int bA    = btile * BTILE + g * 2;    // first batch row of this thread
    const int bB    = bA + 1;
    const int i0    = blockIdx.x * IB;

    float accA[OUT_DIM], accB[OUT_DIM];
#pragma unroll
    for (int e = 0; e < OUT_DIM; e++) { accA[e] = 0.0f; accB[e] = 0.0f; }

    // v from previous routing iteration (per (b, n), 16 floats) in registers
    float vA[OUT_DIM], vB[OUT_DIM];
    if constexpr (P > 0) {
        const float* vsrc = g_v[P - 1];
#pragma unroll
        for (int e = 0; e < OUT_DIM; e++) {
            vA[e] = vsrc[(bA * NC + n) * OUT_DIM + e];
            vB[e] = vsrc[(bB * NC + n) * OUT_DIM + e];
        }
    }

    for (int ii = 0; ii < IB; ii++) {
        const int i = i0 + ii;
        __syncthreads();
        // Stage W[i] (4096 floats = 1024 float4) into padded smem rows.
        {
            const float4* Wg = (const float4*)(W + (size_t)i * (NC * IN_DIM * OUT_DIM));
#pragma unroll
            for (int k = 0; k < 4; k++) {
                int idx4 = tid + 256 * k;     // 0..1023
                int nr   = idx4 >> 5;         // capsule row (32 float4 per row)
                int r4   = idx4 & 31;
                Wsm4[nr * 33 + r4] = Wg[idx4];
            }
        }
        // Stage x[btile rows, i, :]
        if (tid < BTILE * IN_DIM) {
            int bl = tid >> 3, d = tid & 7;
            xsm[bl][d] = x[(size_t)(btile * BTILE + bl) * (IN_CAPS * IN_DIM)
                           + (size_t)i * IN_DIM + d];
        }
        __syncthreads();

        // u_hat[b, i, n, e] = sum_d x[b,i,d] * W[i,n,d,e]   (2 batch rows)
        float uA[OUT_DIM], uB[OUT_DIM];
#pragma unroll
        for (int e = 0; e < OUT_DIM; e++) { uA[e] = 0.0f; uB[e] = 0.0f; }
        const float* wrow = Wsm + n * 132;
#pragma unroll
        for (int d = 0; d < IN_DIM; d++) {
            float xa = xsm[g * 2][d];
            float xb = xsm[g * 2 + 1][d];
            const float4* w4 = (const float4*)(wrow + d * OUT_DIM);
#pragma unroll
            for (int q = 0; q < 4; q++) {
                float4 wv = w4[q];
                uA[4 * q + 0] += xa * wv.x; uA[4 * q + 1] += xa * wv.y;
                uA[4 * q + 2] += xa * wv.z; uA[4 * q + 3] += xa * wv.w;
                uB[4 * q + 0] += xb * wv.x; uB[4 * q + 1] += xb * wv.y;
                uB[4 * q + 2] += xb * wv.z; uB[4 * q + 3] += xb * wv.w;
            }
        }

        if constexpr (P == 0) {
            // c = 1/32 uniformly (softmax of zeros); apply scale in squash.
#pragma unroll
            for (int e = 0; e < OUT_DIM; e++) { accA[e] += uA[e]; accB[e] += uB[e]; }
        } else {
            float lA = 0.0f, lB = 0.0f;
#pragma unroll
            for (int e = 0; e < OUT_DIM; e++) { lA += uA[e] * vA[e]; lB += uB[e] * vB[e]; }
            if constexpr (P == 2) {
                lA += g_logits[((size_t)bA * IN_CAPS + i) * NC + n];
                lB += g_logits[((size_t)bB * IN_CAPS + i) * NC + n];
            } else {
                g_logits[((size_t)bA * IN_CAPS + i) * NC + n] = lA;
                g_logits[((size_t)bB * IN_CAPS + i) * NC + n] = lB;
            }
            // softmax over the 32 capsules = full-warp reduce
            float mA = lA, mB = lB;
#pragma unroll
            for (int o = 16; o > 0; o >>= 1) {
                mA = fmaxf(mA, __shfl_xor_sync(0xffffffffu, mA, o));
                mB = fmaxf(mB, __shfl_xor_sync(0xffffffffu, mB, o));
            }
            float pA = __expf(lA - mA), pB = __expf(lB - mB);
            float ZA = pA, ZB = pB;
#pragma unroll
            for (int o = 16; o > 0; o >>= 1) {
                ZA += __shfl_xor_sync(0xffffffffu, ZA, o);
                ZB += __shfl_xor_sync(0xffffffffu, ZB, o);
            }
            float cA = pA / ZA, cB = pB / ZB;
#pragma unroll
            for (int e = 0; e < OUT_DIM; e++) { accA[e] += cA * uA[e]; accB[e] += cB * uB[e]; }
        }
    }

    // Flush partial sums (addresses disjoint per (b,n,e); ~128 CTAs hit each)
    float* s = g_s[P];
#pragma unroll
    for (int e = 0; e < OUT_DIM; e++) {
        atomicAdd(&s[(bA * NC + n) * OUT_DIM + e], accA[e]);
        atomicAdd(&s[(bB * NC + n) * OUT_DIM + e], accB[e]);
    }
}

// squash(v) = (|v|^2 / (1+|v|^2) / |v|) * v ; scale applied BEFORE squash
template <int K>
__global__ void squash_kernel(float* out_ext) {
    int idx = blockIdx.x * blockDim.x + threadIdx.x;
    if (idx >= BATCH * NC) return;
    const float scale = (K == 0) ? (1.0f / 32.0f) : 1.0f;
    const float* s = g_s[K];
    float* out;
    if constexpr (K == 2) out = out_ext; else out = g_v[K];

    float w[OUT_DIM];
    float s2 = 0.0f;
#pragma unroll
    for (int e = 0; e < OUT_DIM; e++) {
        w[e] = s[idx * OUT_DIM + e] * scale;
        s2 += w[e] * w[e];
    }
    float sc = s2 / ((1.0f + s2) * sqrtf(fmaxf(s2, 1e-30f)));
#pragma unroll
    for (int e = 0; e < OUT_DIM; e++) out[idx * OUT_DIM + e] = sc * w[e];
}

extern "C" void kernel_launch(void* const* d_in, const int* in_sizes, int n_in,
                              void* d_out, int out_size) {
    const float* x = (const float*)d_in[0];   // [64, 2048, 8]
    const float* W = (const float*)d_in[1];   // [2048, 32, 8, 16]
    float* out = (float*)d_out;               // [64, 32, 16]

    zero_kernel<<<(3 * NV + 255) / 256, 256>>>();

    dim3 grid(NIB, NBT);
    dim3 sgrid((BATCH * NC + 255) / 256);

    pass_kernel<0><<<grid, 256>>>(x, W);
    squash_kernel<0><<<sgrid, 256>>>(nullptr);

    pass_kernel<1><<<grid, 256>>>(x, W);
    squash_kernel<1><<<sgrid, 256>>>(nullptr);

    pass_kernel<2><<<grid, 256>>>(x, W);
    squash_kernel<2><<<sgrid, 256>>>(out);
}